// round 1
// baseline (speedup 1.0000x reference)
#include <cuda_runtime.h>

// Problem constants
#define BB  8
#define SEQ 32768
#define HH  96
#define GG  384   // 4*HH

typedef unsigned long long ull;

// -------- scratch (device globals; no allocation allowed) --------
__device__ float g_h0seq[BB * SEQ * HH];   // layer-0 hidden outputs
__device__ float g_xp1[BB * SEQ * GG];     // layer-1 input projections (incl. b1)
__device__ float g_h1seq[BB * SEQ * HH];   // layer-1 hidden outputs

// -------- packed f32x2 helpers (Blackwell) --------
__device__ __forceinline__ ull ffma2(ull a, ull b, ull c) {
    ull d;
    asm("fma.rn.f32x2 %0, %1, %2, %3;" : "=l"(d) : "l"(a), "l"(b), "l"(c));
    return d;
}
__device__ __forceinline__ ull pack2(float x, float y) {
    ull v;
    asm("mov.b64 %0, {%1, %2};" : "=l"(v) : "f"(x), "f"(y));
    return v;
}
__device__ __forceinline__ void unpack2(ull v, float& x, float& y) {
    asm("mov.b64 {%0, %1}, %2;" : "=f"(x), "=f"(y) : "l"(v));
}

// -------- fast activations (EX2/RCP based, ~2ulp) --------
__device__ __forceinline__ float sigmoid_f(float x) {
    float e = __expf(-x);
    return __fdividef(1.0f, 1.0f + e);
}
__device__ __forceinline__ float tanh_f(float x) {
    // tanh(x) = 1 - 2/(exp(2x)+1); saturates correctly at +-inf of expf
    float e = __expf(2.0f * x);
    return 1.0f - __fdividef(2.0f, 1.0f + e);
}

// =====================================================================
// Kernel A: layer-0 recurrence. One CTA per batch, 384 threads.
// Thread g owns W_hh_0 row g in registers (48 x f32x2).
// =====================================================================
__global__ void __launch_bounds__(GG, 1)
lstm0_kernel(const float* __restrict__ x,
             const float* __restrict__ Wih0,
             const float* __restrict__ Whh0,
             const float* __restrict__ b0,
             const float* __restrict__ h0,
             const float* __restrict__ c0)
{
    const int b = blockIdx.x;
    const int g = threadIdx.x;

    __shared__ __align__(16) float h_sh[HH];
    __shared__ float gate_sh[GG];

    // load W_hh row g into registers (row is 384B => 16B aligned)
    ull w[48];
    const ulonglong2* wp = (const ulonglong2*)(Whh0 + g * HH);
#pragma unroll
    for (int k = 0; k < 24; k++) {
        ulonglong2 v = wp[k];
        w[2 * k]     = v.x;
        w[2 * k + 1] = v.y;
    }
    const float wih  = Wih0[g];
    const float bias = b0[g];

    if (g < HH) h_sh[g] = h0[g];
    float c = (g < HH) ? c0[g] : 0.0f;
    __syncthreads();

    const float* xb = x + (size_t)b * SEQ;
    float* hb = g_h0seq + (size_t)b * SEQ * HH;

    const int quad = g / HH;   // 0:i 1:f 2:g 3:o  (warp-uniform)

    float xt_next = __ldg(&xb[0]);
    for (int t = 0; t < SEQ; t++) {
        float xt = xt_next;
        if (t + 1 < SEQ) xt_next = __ldg(&xb[t + 1]);

        ull a0 = pack2(fmaf(xt, wih, bias), 0.0f);
        ull a1 = 0ull;
        const ulonglong2* h4 = (const ulonglong2*)h_sh;
#pragma unroll
        for (int k = 0; k < 24; k++) {
            ulonglong2 hv = h4[k];
            a0 = ffma2(w[2 * k],     hv.x, a0);
            a1 = ffma2(w[2 * k + 1], hv.y, a1);
        }
        float f0x, f0y, f1x, f1y;
        unpack2(a0, f0x, f0y);
        unpack2(a1, f1x, f1y);
        float dot = (f0x + f1x) + (f0y + f1y);

        // activate own gate in-register (parallel over all 12 warps)
        float act = (quad == 2) ? tanh_f(dot) : sigmoid_f(dot);
        gate_sh[g] = act;
        __syncthreads();

        if (g < HH) {
            float iv = gate_sh[g];
            float fv = gate_sh[g + HH];
            float gv = gate_sh[g + 2 * HH];
            float ov = gate_sh[g + 3 * HH];
            c = fmaf(fv, c, iv * gv);
            float hval = ov * tanh_f(c);
            h_sh[g] = hval;
            hb[(size_t)t * HH + g] = hval;
        }
        __syncthreads();
    }
}

// =====================================================================
// Kernel B: xp1[b,t,g] = sum_k h0seq[b,t,k]*Wih1[g,k] + b1[g]
// Fully parallel over t. 384 threads, W_ih_1 rows in registers,
// double-buffered shared staging of h0[t].
// =====================================================================
#define TB 512
__global__ void __launch_bounds__(GG, 1)
xp1_kernel(const float* __restrict__ Wih1,
           const float* __restrict__ b1)
{
    const int b  = blockIdx.y;
    const int g  = threadIdx.x;
    const int t0 = blockIdx.x * TB;
    const int t1 = t0 + TB;   // SEQ % TB == 0

    ull w[48];
    const ulonglong2* wp = (const ulonglong2*)(Wih1 + g * HH);
#pragma unroll
    for (int k = 0; k < 24; k++) {
        ulonglong2 v = wp[k];
        w[2 * k]     = v.x;
        w[2 * k + 1] = v.y;
    }
    const float bias = b1[g];

    __shared__ __align__(16) float buf[2][HH];
    const float* hb = g_h0seq + (size_t)b * SEQ * HH;
    float* xpb = g_xp1 + (size_t)b * SEQ * GG;

    if (g < 24)
        ((float4*)buf[0])[g] = ((const float4*)(hb + (size_t)t0 * HH))[g];
    __syncthreads();

    int cur = 0;
    for (int t = t0; t < t1; t++) {
        if (g < 24 && t + 1 < SEQ)
            ((float4*)buf[cur ^ 1])[g] = ((const float4*)(hb + (size_t)(t + 1) * HH))[g];

        ull a0 = pack2(bias, 0.0f);
        ull a1 = 0ull;
        const ulonglong2* h4 = (const ulonglong2*)buf[cur];
#pragma unroll
        for (int k = 0; k < 24; k++) {
            ulonglong2 hv = h4[k];
            a0 = ffma2(w[2 * k],     hv.x, a0);
            a1 = ffma2(w[2 * k + 1], hv.y, a1);
        }
        float f0x, f0y, f1x, f1y;
        unpack2(a0, f0x, f0y);
        unpack2(a1, f1x, f1y);
        xpb[(size_t)t * GG + g] = (f0x + f1x) + (f0y + f1y);

        __syncthreads();
        cur ^= 1;
    }
}

// =====================================================================
// Kernel C: layer-1 recurrence. Same as A but xp comes from g_xp1.
// =====================================================================
__global__ void __launch_bounds__(GG, 1)
lstm1_kernel(const float* __restrict__ Whh1,
             const float* __restrict__ h0,   // already offset to layer 1
             const float* __restrict__ c0)
{
    const int b = blockIdx.x;
    const int g = threadIdx.x;

    __shared__ __align__(16) float h_sh[HH];
    __shared__ float gate_sh[GG];

    ull w[48];
    const ulonglong2* wp = (const ulonglong2*)(Whh1 + g * HH);
#pragma unroll
    for (int k = 0; k < 24; k++) {
        ulonglong2 v = wp[k];
        w[2 * k]     = v.x;
        w[2 * k + 1] = v.y;
    }

    if (g < HH) h_sh[g] = h0[g];
    float c = (g < HH) ? c0[g] : 0.0f;
    __syncthreads();

    const float* xpb = g_xp1 + (size_t)b * SEQ * GG;
    float* hb = g_h1seq + (size_t)b * SEQ * HH;

    const int quad = g / HH;

    float xp_next = __ldg(&xpb[g]);
    for (int t = 0; t < SEQ; t++) {
        float xp = xp_next;
        if (t + 1 < SEQ) xp_next = __ldg(&xpb[(size_t)(t + 1) * GG + g]);

        ull a0 = pack2(xp, 0.0f);
        ull a1 = 0ull;
        const ulonglong2* h4 = (const ulonglong2*)h_sh;
#pragma unroll
        for (int k = 0; k < 24; k++) {
            ulonglong2 hv = h4[k];
            a0 = ffma2(w[2 * k],     hv.x, a0);
            a1 = ffma2(w[2 * k + 1], hv.y, a1);
        }
        float f0x, f0y, f1x, f1y;
        unpack2(a0, f0x, f0y);
        unpack2(a1, f1x, f1y);
        float dot = (f0x + f1x) + (f0y + f1y);

        float act = (quad == 2) ? tanh_f(dot) : sigmoid_f(dot);
        gate_sh[g] = act;
        __syncthreads();

        if (g < HH) {
            float iv = gate_sh[g];
            float fv = gate_sh[g + HH];
            float gv = gate_sh[g + 2 * HH];
            float ov = gate_sh[g + 3 * HH];
            c = fmaf(fv, c, iv * gv);
            float hval = ov * tanh_f(c);
            h_sh[g] = hval;
            hb[(size_t)t * HH + g] = hval;
        }
        __syncthreads();
    }
}

// =====================================================================
// Kernel D: out[b,t] = dot(h1seq[b,t,:], head_w) + head_b
// =====================================================================
__global__ void __launch_bounds__(256)
head_kernel(const float* __restrict__ head_w,
            const float* __restrict__ head_b,
            float* __restrict__ out)
{
    int idx = blockIdx.x * blockDim.x + threadIdx.x;   // over B*SEQ
    if (idx >= BB * SEQ) return;
    const float4* hp = (const float4*)(g_h1seq + (size_t)idx * HH);
    const float4* wp = (const float4*)head_w;
    float acc = 0.0f;
#pragma unroll
    for (int k = 0; k < 24; k++) {
        float4 a = __ldg(&hp[k]);
        float4 wv = __ldg(&wp[k]);
        acc += a.x * wv.x + a.y * wv.y + a.z * wv.z + a.w * wv.w;
    }
    out[idx] = acc + __ldg(head_b);
}

// =====================================================================
// launch
// =====================================================================
extern "C" void kernel_launch(void* const* d_in, const int* in_sizes, int n_in,
                              void* d_out, int out_size)
{
    (void)in_sizes; (void)n_in; (void)out_size;
    const float* x      = (const float*)d_in[0];
    const float* W_ih_0 = (const float*)d_in[1];
    const float* W_hh_0 = (const float*)d_in[2];
    const float* b_0    = (const float*)d_in[3];
    const float* W_ih_1 = (const float*)d_in[4];
    const float* W_hh_1 = (const float*)d_in[5];
    const float* b_1    = (const float*)d_in[6];
    const float* h0     = (const float*)d_in[7];
    const float* c0     = (const float*)d_in[8];
    const float* head_w = (const float*)d_in[9];
    const float* head_b = (const float*)d_in[10];
    float* out = (float*)d_out;

    lstm0_kernel<<<BB, GG>>>(x, W_ih_0, W_hh_0, b_0, h0, c0);
    xp1_kernel<<<dim3(SEQ / TB, BB), GG>>>(W_ih_1, b_1);
    lstm1_kernel<<<BB, GG>>>(W_hh_1, h0 + HH, c0 + HH);
    head_kernel<<<(BB * SEQ + 255) / 256, 256>>>(head_w, head_b, out);
}